// round 7
// baseline (speedup 1.0000x reference)
#include <cuda_runtime.h>
#include <cuda_bf16.h>
#include <math.h>
#include <stdint.h>

#define NN 16384
#define DD 64

// Scratch (static __device__ — allocation is forbidden).
__device__ __align__(16) float g_h1[NN * DD];    // z @ W
__device__ __align__(16) float g_h2[NN * DD];    // GCN output (pre-relu)
__device__ float g_deg[NN];
__device__ int   g_is64;                         // edge_index dtype flag

// ---------------- fused init: deg self-loops + dtype probe ----------------
// dtype probe: sample 256 odd u32 words of the edge buffer. All zero -> ids
// are int64 (high halves of values < 16384); any nonzero -> int32.
// P(false int64 | int32 random ids) = 16384^-256 ~ 0.
__global__ void fused_init_kernel(const unsigned* __restrict__ ei32) {
    int i = blockIdx.x * 256 + threadIdx.x;
    if (i < NN) g_deg[i] = 1.0f;
    if (blockIdx.x == 0) {
        __shared__ int any_nonzero;
        if (threadIdx.x == 0) any_nonzero = 0;
        __syncthreads();
        if (ei32[2 * threadIdx.x + 1] != 0u) any_nonzero = 1;
        __syncthreads();
        if (threadIdx.x == 0) g_is64 = any_nonzero ? 0 : 1;
    }
}
__device__ __forceinline__ int edge_get(const void* ei, int is64, size_t idx) {
    if (is64) return (int)((const long long*)ei)[idx];
    return ((const int*)ei)[idx];
}

// ---------------- deg count over cols ----------------
__global__ void deg_count_kernel(const void* __restrict__ ei, int E) {
    int e = blockIdx.x * 256 + threadIdx.x;
    if (e >= E) return;
    int c = edge_get(ei, g_is64, (size_t)E + e);
    if ((unsigned)c < NN) atomicAdd(&g_deg[c], 1.0f);
}

// ---------------- fused: h1 = z@W ; h2 = h1*rsqrt(deg)^2 + b ----------------
__global__ void linear_fused_kernel(const float* __restrict__ z,
                                    const float* __restrict__ W,
                                    const float* __restrict__ b) {
    __shared__ float Ws[DD * DD];
    __shared__ float zs[4 * DD];
    int tid = threadIdx.x;                 // 256 threads
    int j = tid & 63;
    int rl = tid >> 6;
    for (int i = tid; i < DD * DD; i += 256) Ws[i] = W[i];
    size_t gi = (size_t)blockIdx.x * 256 + tid;
    zs[tid] = z[gi];
    __syncthreads();
    float s = 0.0f;
#pragma unroll
    for (int k = 0; k < DD; k++) s = fmaf(zs[rl * DD + k], Ws[k * DD + j], s);
    int node = (int)(gi >> 6);
    float di = rsqrtf(g_deg[node]);
    g_h1[gi] = s;
    g_h2[gi] = s * di * di + b[j];
}

// ---------------- edge scatter: h2[col] += h1[row]*norm ----------------
// 8 lanes per edge, each lane covers 32B via two red.v4.
__global__ void scatter_kernel(const void* __restrict__ ei, int E) {
    int t = blockIdx.x * 256 + threadIdx.x;  // over E*8
    int e = t >> 3;
    int q = t & 7;
    if (e >= E) return;
    int is64 = g_is64;
    int r = edge_get(ei, is64, (size_t)e);
    int c = edge_get(ei, is64, (size_t)E + e);
    if ((unsigned)r >= NN || (unsigned)c >= NN) return;
    float norm = rsqrtf(g_deg[r]) * rsqrtf(g_deg[c]);
    const float4 v0 = *(const float4*)&g_h1[((size_t)r << 6) + q * 8];
    const float4 v1 = *(const float4*)&g_h1[((size_t)r << 6) + q * 8 + 4];
    float* dst = &g_h2[((size_t)c << 6) + q * 8];
    asm volatile("red.global.add.v4.f32 [%0], {%1,%2,%3,%4};"
                 :: "l"(dst), "f"(v0.x * norm), "f"(v0.y * norm),
                    "f"(v0.z * norm), "f"(v0.w * norm) : "memory");
    asm volatile("red.global.add.v4.f32 [%0], {%1,%2,%3,%4};"
                 :: "l"(dst + 4), "f"(v1.x * norm), "f"(v1.y * norm),
                    "f"(v1.z * norm), "f"(v1.w * norm) : "memory");
}

// ---------------- A = relu(h2) @ relu(h2)^T via mma.sync tf32 ----------------
// Triangular 1-D grid (8256 CTAs), 128x128 tile, K=64 single-shot smem stage,
// 8 warps 4(M)x2(N). Natural [node][k] layout, stride 68 -> conflict-free.
// Mirror tile written from registers.
#define SK 68

__device__ __forceinline__ uint32_t f2tf32(float x) {
    uint32_t r;
    asm("cvt.rna.tf32.f32 %0, %1;" : "=r"(r) : "f"(x));
    return r;
}
__device__ __forceinline__ void mma_tf32(float* d, const uint32_t* a, const uint32_t* b) {
    asm("mma.sync.aligned.m16n8k8.row.col.f32.tf32.tf32.f32 "
        "{%0,%1,%2,%3}, {%4,%5,%6,%7}, {%8,%9}, {%0,%1,%2,%3};"
        : "+f"(d[0]), "+f"(d[1]), "+f"(d[2]), "+f"(d[3])
        : "r"(a[0]), "r"(a[1]), "r"(a[2]), "r"(a[3]),
          "r"(b[0]), "r"(b[1]));
}
__device__ __forceinline__ void stcs2(float* p, float x, float y) {
    asm volatile("st.global.cs.v2.f32 [%0], {%1,%2};" :: "l"(p), "f"(x), "f"(y) : "memory");
}
__device__ __forceinline__ void stcs1(float* p, float x) {
    asm volatile("st.global.cs.f32 [%0], %1;" :: "l"(p), "f"(x) : "memory");
}

__global__ void __launch_bounds__(256, 2) gemm_tf32_kernel(float* __restrict__ C, int n) {
    // Decode linear triangular index -> (by, bx), bx <= by.
    int idx = blockIdx.x;
    int by = (int)((sqrtf(8.0f * (float)idx + 1.0f) - 1.0f) * 0.5f);
    while ((by + 1) * (by + 2) / 2 <= idx) by++;
    while (by * (by + 1) / 2 > idx) by--;
    int bx = idx - by * (by + 1) / 2;

    extern __shared__ uint32_t sm[];
    uint32_t* As = sm;              // 128*SK
    uint32_t* Bs = sm + 128 * SK;   // 128*SK

    int tid  = threadIdx.x;
    int lane = tid & 31, wid = tid >> 5;
    int g    = lane >> 2, tig = lane & 3;     // groupID, threadID_in_group
    int wm   = wid & 3,  wn  = wid >> 2;      // warp grid 4x2

    const float4* H4 = (const float4*)g_h2;

    // Stage full 128x64 tiles for A and B (relu + tf32 convert).
#pragma unroll
    for (int i = 0; i < 8; i++) {
        int idx2 = i * 256 + tid;
        int row = idx2 >> 4, kq = idx2 & 15;
        float4 va = H4[(size_t)(by * 128 + row) * 16 + kq];
        uint4 ta;
        ta.x = f2tf32(fmaxf(va.x, 0.f)); ta.y = f2tf32(fmaxf(va.y, 0.f));
        ta.z = f2tf32(fmaxf(va.z, 0.f)); ta.w = f2tf32(fmaxf(va.w, 0.f));
        *(uint4*)&As[row * SK + kq * 4] = ta;
        float4 vb = H4[(size_t)(bx * 128 + row) * 16 + kq];
        uint4 tb;
        tb.x = f2tf32(fmaxf(vb.x, 0.f)); tb.y = f2tf32(fmaxf(vb.y, 0.f));
        tb.z = f2tf32(fmaxf(vb.z, 0.f)); tb.w = f2tf32(fmaxf(vb.w, 0.f));
        *(uint4*)&Bs[row * SK + kq * 4] = tb;
    }
    __syncthreads();

    float acc[2][8][4];
#pragma unroll
    for (int mf = 0; mf < 2; mf++)
#pragma unroll
        for (int nf = 0; nf < 8; nf++)
#pragma unroll
            for (int i = 0; i < 4; i++) acc[mf][nf][i] = 0.0f;

#pragma unroll
    for (int ks = 0; ks < 8; ks++) {
        int k0 = ks * 8;
        uint32_t a[2][4], b[8][2];
#pragma unroll
        for (int mf = 0; mf < 2; mf++) {
            int r = wm * 32 + mf * 16 + g;
            a[mf][0] = As[r * SK + k0 + tig];
            a[mf][1] = As[(r + 8) * SK + k0 + tig];
            a[mf][2] = As[r * SK + k0 + tig + 4];
            a[mf][3] = As[(r + 8) * SK + k0 + tig + 4];
        }
#pragma unroll
        for (int nf = 0; nf < 8; nf++) {
            int c = wn * 64 + nf * 8 + g;
            b[nf][0] = Bs[c * SK + k0 + tig];
            b[nf][1] = Bs[c * SK + k0 + tig + 4];
        }
#pragma unroll
        for (int mf = 0; mf < 2; mf++)
#pragma unroll
            for (int nf = 0; nf < 8; nf++)
                mma_tf32(acc[mf][nf], a[mf], b[nf]);
    }

    // Direct (lower) tile: streaming float2 stores.
#pragma unroll
    for (int mf = 0; mf < 2; mf++) {
        int row0 = by * 128 + wm * 32 + mf * 16 + g;
#pragma unroll
        for (int nf = 0; nf < 8; nf++) {
            int col = bx * 128 + wn * 64 + nf * 8 + 2 * tig;
            stcs2(&C[(size_t)row0 * n + col],       acc[mf][nf][0], acc[mf][nf][1]);
            stcs2(&C[(size_t)(row0 + 8) * n + col], acc[mf][nf][2], acc[mf][nf][3]);
        }
    }
    // Mirror (upper) tile from registers.
    if (bx != by) {
#pragma unroll
        for (int mf = 0; mf < 2; mf++) {
            int row0 = by * 128 + wm * 32 + mf * 16 + g;
#pragma unroll
            for (int nf = 0; nf < 8; nf++) {
                int col = bx * 128 + wn * 64 + nf * 8 + 2 * tig;
                stcs1(&C[(size_t)col * n + row0],           acc[mf][nf][0]);
                stcs1(&C[(size_t)(col + 1) * n + row0],     acc[mf][nf][1]);
                stcs1(&C[(size_t)col * n + row0 + 8],       acc[mf][nf][2]);
                stcs1(&C[(size_t)(col + 1) * n + row0 + 8], acc[mf][nf][3]);
            }
        }
    }
}

// ---------------- Launcher ----------------
extern "C" void kernel_launch(void* const* d_in, const int* in_sizes, int n_in,
                              void* d_out, int out_size) {
    const float* z  = (const float*)d_in[0];
    const void*  ei = d_in[1];              // int32 or int64 — probed on device
    const float* W  = (const float*)d_in[2];
    const float* b  = (const float*)d_in[3];
    float* out = (float*)d_out;

    int n = in_sizes[0] / DD;        // 16384
    int E = in_sizes[1] / 2;         // 524288

    fused_init_kernel<<<(n + 255) / 256, 256>>>((const unsigned*)ei);
    deg_count_kernel<<<(E + 255) / 256, 256>>>(ei, E);
    linear_fused_kernel<<<n * DD / 256, 256>>>(z, W, b);
    scatter_kernel<<<(E * 8 + 255) / 256, 256>>>(ei, E);

    // A_hat = relu(h2) @ relu(h2)^T  (symmetric: triangular grid + mirror)
    size_t smem_bytes = (size_t)(2 * 128 * SK) * sizeof(uint32_t);  // 69632
    cudaFuncSetAttribute(gemm_tf32_kernel,
                         cudaFuncAttributeMaxDynamicSharedMemorySize,
                         (int)smem_bytes);
    int nb = n / 128;
    int tri = nb * (nb + 1) / 2;     // 8256
    gemm_tf32_kernel<<<tri, 256, smem_bytes>>>(out, n);
}